// round 1
// baseline (speedup 1.0000x reference)
#include <cuda_runtime.h>

#define D 128
#define MAX_DRUG 10000
#define MAX_DIS  15000

// Scratch for projected embeddings (allocation-free per harness rules).
__device__ float g_A[MAX_DRUG * D];   // z_drug @ W1[0:128] + b1
__device__ float g_B[MAX_DIS  * D];   // z_disease @ W1[128:256]

// out[n][j] = sum_k Z[n][k] * W1[(koff+k)*D + j]  (+ b1[j] if addb1)
// Tile: 32 rows x 128 cols per block, 256 threads, each thread 16 outputs.
__global__ __launch_bounds__(256) void proj_kernel(
    const float* __restrict__ Z,
    const float* __restrict__ W1,
    int koff,
    const float* __restrict__ b1,
    float* __restrict__ out,
    int N, int addb1)
{
    __shared__ float Zs[32][132];   // +4 pad: rows land on distinct banks
    __shared__ float W1s[32][128];

    const int r0 = blockIdx.x * 32;
    const int t  = threadIdx.x;
    const int r  = t >> 3;   // 0..31 (output row within tile)
    const int cg = t & 7;    // 0..7  (16-col group)

    // Load Z tile [32 x 128] as float4s (row base 132*4=528B is 16B-aligned).
    for (int i = t; i < 32 * 32; i += 256) {
        int rr = i >> 5;
        int c4 = i & 31;
        float4 v = make_float4(0.f, 0.f, 0.f, 0.f);
        if (r0 + rr < N)
            v = reinterpret_cast<const float4*>(Z + (size_t)(r0 + rr) * D)[c4];
        *reinterpret_cast<float4*>(&Zs[rr][c4 * 4]) = v;
    }

    float acc[16];
#pragma unroll
    for (int j = 0; j < 16; j++) acc[j] = 0.f;

    for (int kc = 0; kc < 4; kc++) {
        __syncthreads();   // Zs ready (iter0) / W1s consumed (iter>0)
        // Load W1 chunk: k rows [kc*32, kc*32+32), all 128 cols.
        for (int i = t; i < 32 * 32; i += 256) {
            int kk = i >> 5;
            int c4 = i & 31;
            *reinterpret_cast<float4*>(&W1s[kk][c4 * 4]) =
                reinterpret_cast<const float4*>(
                    W1 + (size_t)(koff + kc * 32 + kk) * D)[c4];
        }
        __syncthreads();
#pragma unroll
        for (int kk = 0; kk < 32; kk++) {
            float z = Zs[r][kc * 32 + kk];
#pragma unroll
            for (int j = 0; j < 16; j++)
                acc[j] += z * W1s[kk][cg * 16 + j];
        }
    }

    if (r0 + r < N) {
        float* o = out + (size_t)(r0 + r) * D + cg * 16;
#pragma unroll
        for (int j = 0; j < 16; j++) {
            float v = acc[j];
            if (addb1) v += b1[cg * 16 + j];
            o[j] = v;
        }
    }
}

// Warp per 2 edges: lane l holds A[r][4l..4l+3] + B[c][4l..4l+3] and
// W2[4l..4l+3] in registers; relu+dot, butterfly reduce, lane 0 stores.
__global__ __launch_bounds__(256) void edge_kernel(
    const int* __restrict__ row, const int* __restrict__ col,
    const float* __restrict__ W2, const float* __restrict__ b2,
    float* __restrict__ out, int E)
{
    const int lane = threadIdx.x & 31;
    const int warp = blockIdx.x * (blockDim.x >> 5) + (threadIdx.x >> 5);
    const int e0 = warp * 2;
    if (e0 >= E) return;

    const float4 w2 = reinterpret_cast<const float4*>(W2)[lane];
    const float bias = b2[0];

    const bool has1 = (e0 + 1) < E;
    const int r0i = row[e0];
    const int c0i = col[e0];
    const int r1i = has1 ? row[e0 + 1] : r0i;
    const int c1i = has1 ? col[e0 + 1] : c0i;

    // Front-batched: 4 independent LDG.128 in flight vs L2 latency.
    const float4 a0 = reinterpret_cast<const float4*>(g_A + (size_t)r0i * D)[lane];
    const float4 b0 = reinterpret_cast<const float4*>(g_B + (size_t)c0i * D)[lane];
    const float4 a1 = reinterpret_cast<const float4*>(g_A + (size_t)r1i * D)[lane];
    const float4 b1 = reinterpret_cast<const float4*>(g_B + (size_t)c1i * D)[lane];

    float s0 = fmaxf(a0.x + b0.x, 0.f) * w2.x
             + fmaxf(a0.y + b0.y, 0.f) * w2.y
             + fmaxf(a0.z + b0.z, 0.f) * w2.z
             + fmaxf(a0.w + b0.w, 0.f) * w2.w;
    float s1 = fmaxf(a1.x + b1.x, 0.f) * w2.x
             + fmaxf(a1.y + b1.y, 0.f) * w2.y
             + fmaxf(a1.z + b1.z, 0.f) * w2.z
             + fmaxf(a1.w + b1.w, 0.f) * w2.w;

#pragma unroll
    for (int off = 16; off > 0; off >>= 1) {
        s0 += __shfl_xor_sync(0xffffffffu, s0, off);
        s1 += __shfl_xor_sync(0xffffffffu, s1, off);
    }

    if (lane == 0) {
        out[e0] = s0 + bias;
        if (has1) out[e0 + 1] = s1 + bias;
    }
}

extern "C" void kernel_launch(void* const* d_in, const int* in_sizes, int n_in,
                              void* d_out, int out_size)
{
    const float* z_drug = (const float*)d_in[0];
    const float* z_dis  = (const float*)d_in[1];
    const int*   row    = (const int*)  d_in[2];
    const int*   col    = (const int*)  d_in[3];
    const float* W1     = (const float*)d_in[4];
    const float* b1     = (const float*)d_in[5];
    const float* W2     = (const float*)d_in[6];
    const float* b2     = (const float*)d_in[7];
    float* out = (float*)d_out;

    const int n_drug = in_sizes[0] / D;
    const int n_dis  = in_sizes[1] / D;
    const int E      = in_sizes[2];

    float *dA = nullptr, *dB = nullptr;
    cudaGetSymbolAddress((void**)&dA, g_A);
    cudaGetSymbolAddress((void**)&dB, g_B);

    // Phase 1: node projections (z @ W1 halves), b1 folded into A.
    proj_kernel<<<(n_drug + 31) / 32, 256>>>(z_drug, W1, 0,   b1, dA, n_drug, 1);
    proj_kernel<<<(n_dis  + 31) / 32, 256>>>(z_dis,  W1, 128, b1, dB, n_dis,  0);

    // Phase 2: per-edge gather + relu + dot(W2). 2 edges per warp.
    const int warps  = (E + 1) / 2;
    const int blocks = (warps + 7) / 8;
    edge_kernel<<<blocks, 256>>>(row, col, W2, b2, out, E);
}

// round 2
// speedup vs baseline: 2.9961x; 2.9961x over previous
#include <cuda_runtime.h>

#define D 128
#define MAX_DRUG 10000
#define MAX_DIS  15000
#define KC 16          // k-chunk per smem stage

__device__ float g_A[MAX_DRUG * D];   // z_drug    @ W1[0:128]  + b1
__device__ float g_B[MAX_DIS  * D];   // z_disease @ W1[128:256]

// Fused projection: computes BOTH A = z_drug@W1_top + b1 and
// B = z_dis@W1_bot in one launch. One block per 128x128 output tile,
// 256 threads, 8x8 register tile per thread.
__global__ __launch_bounds__(256) void proj2_kernel(
    const float* __restrict__ Zd, const float* __restrict__ Zs_,
    int n_drug, int n_dis,
    const float* __restrict__ W1, const float* __restrict__ b1,
    float* __restrict__ A, float* __restrict__ B)
{
    const int tiles_drug = (n_drug + 127) / 128;

    const float* Z;
    float* out;
    int N, koff, addb;
    int tile = blockIdx.x;
    if (tile < tiles_drug) { Z = Zd;  out = A; N = n_drug; koff = 0;   addb = 1; }
    else { tile -= tiles_drug; Z = Zs_; out = B; N = n_dis; koff = 128; addb = 0; }
    const int r0 = tile * 128;

    __shared__ float Zt[KC][128];   // k-major (transposed Z tile)
    __shared__ float Wt[KC][128];

    const int t  = threadIdx.x;
    const int tx = t & 15;          // col group: cols tx*8 .. tx*8+7
    const int ty = t >> 4;          // row group: rows ty*8 .. ty*8+7

    float acc[8][8];
#pragma unroll
    for (int i = 0; i < 8; i++)
#pragma unroll
        for (int j = 0; j < 8; j++) acc[i][j] = 0.f;

    for (int kc = 0; kc < D; kc += KC) {
        __syncthreads();   // previous stage fully consumed

        // Z tile: rows r0..r0+127, k in [kc, kc+16). 512 float4 loads.
        // i = k4*128 + rr  ->  within a warp rr spans 32 consecutive rows:
        // transposed STS hits all 32 banks (conflict-free).
#pragma unroll
        for (int i = t; i < 512; i += 256) {
            int rr = i & 127;
            int k4 = i >> 7;     // which float4 of the 16-k chunk (0..3)
            float4 v = make_float4(0.f, 0.f, 0.f, 0.f);
            if (r0 + rr < N)
                v = *reinterpret_cast<const float4*>(
                        Z + (size_t)(r0 + rr) * D + kc + k4 * 4);
            Zt[k4 * 4 + 0][rr] = v.x;
            Zt[k4 * 4 + 1][rr] = v.y;
            Zt[k4 * 4 + 2][rr] = v.z;
            Zt[k4 * 4 + 3][rr] = v.w;
        }
        // W1 chunk: k rows [koff+kc, +16), all 128 cols. Coalesced float4.
#pragma unroll
        for (int i = t; i < 512; i += 256) {
            int kk = i >> 5;
            int c4 = i & 31;
            *reinterpret_cast<float4*>(&Wt[kk][c4 * 4]) =
                *reinterpret_cast<const float4*>(
                    W1 + (size_t)(koff + kc + kk) * D + c4 * 4);
        }
        __syncthreads();

#pragma unroll
        for (int kk = 0; kk < KC; kk++) {
            float af[8], bf[8];
            // A-frag: 8 consecutive rows -> 2x LDS.128, warp-broadcast per phase
            *reinterpret_cast<float4*>(af)     = *reinterpret_cast<float4*>(&Zt[kk][ty * 8]);
            *reinterpret_cast<float4*>(af + 4) = *reinterpret_cast<float4*>(&Zt[kk][ty * 8 + 4]);
            // B-frag: 8 consecutive cols -> 2x LDS.128, all 32 banks once
            *reinterpret_cast<float4*>(bf)     = *reinterpret_cast<float4*>(&Wt[kk][tx * 8]);
            *reinterpret_cast<float4*>(bf + 4) = *reinterpret_cast<float4*>(&Wt[kk][tx * 8 + 4]);
#pragma unroll
            for (int i = 0; i < 8; i++)
#pragma unroll
                for (int j = 0; j < 8; j++)
                    acc[i][j] = fmaf(af[i], bf[j], acc[i][j]);
        }
    }

    // Epilogue: rows r0+ty*8+i, cols tx*8+j. Optional bias.
    float bias[8];
#pragma unroll
    for (int j = 0; j < 8; j++) bias[j] = addb ? b1[tx * 8 + j] : 0.f;

#pragma unroll
    for (int i = 0; i < 8; i++) {
        int r = r0 + ty * 8 + i;
        if (r < N) {
            float4 v0, v1;
            v0.x = acc[i][0] + bias[0]; v0.y = acc[i][1] + bias[1];
            v0.z = acc[i][2] + bias[2]; v0.w = acc[i][3] + bias[3];
            v1.x = acc[i][4] + bias[4]; v1.y = acc[i][5] + bias[5];
            v1.z = acc[i][6] + bias[6]; v1.w = acc[i][7] + bias[7];
            float4* o = reinterpret_cast<float4*>(out + (size_t)r * D + tx * 8);
            o[0] = v0;
            o[1] = v1;
        }
    }
}

// Warp per 2 edges: lane l holds A[r][4l..4l+3] + B[c][4l..4l+3] and
// W2[4l..4l+3] in registers; relu+dot, butterfly reduce, lane 0 stores.
__global__ __launch_bounds__(256) void edge_kernel(
    const int* __restrict__ row, const int* __restrict__ col,
    const float* __restrict__ W2, const float* __restrict__ b2,
    float* __restrict__ out, int E)
{
    const int lane = threadIdx.x & 31;
    const int warp = blockIdx.x * (blockDim.x >> 5) + (threadIdx.x >> 5);
    const int e0 = warp * 2;
    if (e0 >= E) return;

    const float4 w2 = reinterpret_cast<const float4*>(W2)[lane];
    const float bias = b2[0];

    const bool has1 = (e0 + 1) < E;
    const int r0i = row[e0];
    const int c0i = col[e0];
    const int r1i = has1 ? row[e0 + 1] : r0i;
    const int c1i = has1 ? col[e0 + 1] : c0i;

    const float4 a0 = reinterpret_cast<const float4*>(g_A + (size_t)r0i * D)[lane];
    const float4 b0 = reinterpret_cast<const float4*>(g_B + (size_t)c0i * D)[lane];
    const float4 a1 = reinterpret_cast<const float4*>(g_A + (size_t)r1i * D)[lane];
    const float4 b1 = reinterpret_cast<const float4*>(g_B + (size_t)c1i * D)[lane];

    float s0 = fmaxf(a0.x + b0.x, 0.f) * w2.x
             + fmaxf(a0.y + b0.y, 0.f) * w2.y
             + fmaxf(a0.z + b0.z, 0.f) * w2.z
             + fmaxf(a0.w + b0.w, 0.f) * w2.w;
    float s1 = fmaxf(a1.x + b1.x, 0.f) * w2.x
             + fmaxf(a1.y + b1.y, 0.f) * w2.y
             + fmaxf(a1.z + b1.z, 0.f) * w2.z
             + fmaxf(a1.w + b1.w, 0.f) * w2.w;

#pragma unroll
    for (int off = 16; off > 0; off >>= 1) {
        s0 += __shfl_xor_sync(0xffffffffu, s0, off);
        s1 += __shfl_xor_sync(0xffffffffu, s1, off);
    }

    if (lane == 0) {
        out[e0] = s0 + bias;
        if (has1) out[e0 + 1] = s1 + bias;
    }
}

extern "C" void kernel_launch(void* const* d_in, const int* in_sizes, int n_in,
                              void* d_out, int out_size)
{
    const float* z_drug = (const float*)d_in[0];
    const float* z_dis  = (const float*)d_in[1];
    const int*   row    = (const int*)  d_in[2];
    const int*   col    = (const int*)  d_in[3];
    const float* W1     = (const float*)d_in[4];
    const float* b1     = (const float*)d_in[5];
    const float* W2     = (const float*)d_in[6];
    const float* b2     = (const float*)d_in[7];
    float* out = (float*)d_out;

    const int n_drug = in_sizes[0] / D;
    const int n_dis  = in_sizes[1] / D;
    const int E      = in_sizes[2];

    float *dA = nullptr, *dB = nullptr;
    cudaGetSymbolAddress((void**)&dA, g_A);
    cudaGetSymbolAddress((void**)&dB, g_B);

    // Phase 1: both node projections in ONE launch.
    const int tiles = (n_drug + 127) / 128 + (n_dis + 127) / 128;
    proj2_kernel<<<tiles, 256>>>(z_drug, z_dis, n_drug, n_dis, W1, b1, dA, dB);

    // Phase 2: per-edge gather + relu + dot(W2). 2 edges per warp.
    const int warps  = (E + 1) / 2;
    const int blocks = (warps + 7) / 8;
    edge_kernel<<<blocks, 256>>>(row, col, W2, b2, out, E);
}

// round 3
// speedup vs baseline: 3.9885x; 1.3312x over previous
#include <cuda_runtime.h>
#include <cuda_fp16.h>

#define D 128
#define MAX_DRUG 10000
#define MAX_DIS  15000
#define KC 16          // k-chunk per smem stage

// Projected embeddings stored in fp16 (computed in fp32, rounded once).
__device__ __half g_Ah[MAX_DRUG * D];   // z_drug    @ W1[0:128]  + b1
__device__ __half g_Bh[MAX_DIS  * D];   // z_disease @ W1[128:256]

// Fused projection: A = z_drug@W1_top + b1 and B = z_dis@W1_bot in one
// launch. One block per 128x128 output tile, 256 threads, 8x8 register
// tile per thread. Epilogue rounds to fp16.
__global__ __launch_bounds__(256) void proj2_kernel(
    const float* __restrict__ Zd, const float* __restrict__ Zs_,
    int n_drug, int n_dis,
    const float* __restrict__ W1, const float* __restrict__ b1,
    __half* __restrict__ A, __half* __restrict__ B)
{
    const int tiles_drug = (n_drug + 127) / 128;

    const float* Z;
    __half* out;
    int N, koff, addb;
    int tile = blockIdx.x;
    if (tile < tiles_drug) { Z = Zd;  out = A; N = n_drug; koff = 0;   addb = 1; }
    else { tile -= tiles_drug; Z = Zs_; out = B; N = n_dis; koff = 128; addb = 0; }
    const int r0 = tile * 128;

    __shared__ float Zt[KC][128];   // k-major (transposed Z tile)
    __shared__ float Wt[KC][128];

    const int t  = threadIdx.x;
    const int tx = t & 15;          // col group: cols tx*8 .. tx*8+7
    const int ty = t >> 4;          // row group: rows ty*8 .. ty*8+7

    float acc[8][8];
#pragma unroll
    for (int i = 0; i < 8; i++)
#pragma unroll
        for (int j = 0; j < 8; j++) acc[i][j] = 0.f;

    for (int kc = 0; kc < D; kc += KC) {
        __syncthreads();   // previous stage fully consumed

        // Z tile: rows r0..r0+127, k in [kc, kc+16). Transposed STS.
#pragma unroll
        for (int i = t; i < 512; i += 256) {
            int rr = i & 127;
            int k4 = i >> 7;
            float4 v = make_float4(0.f, 0.f, 0.f, 0.f);
            if (r0 + rr < N)
                v = *reinterpret_cast<const float4*>(
                        Z + (size_t)(r0 + rr) * D + kc + k4 * 4);
            Zt[k4 * 4 + 0][rr] = v.x;
            Zt[k4 * 4 + 1][rr] = v.y;
            Zt[k4 * 4 + 2][rr] = v.z;
            Zt[k4 * 4 + 3][rr] = v.w;
        }
        // W1 chunk: k rows [koff+kc, +16), all 128 cols. Coalesced float4.
#pragma unroll
        for (int i = t; i < 512; i += 256) {
            int kk = i >> 5;
            int c4 = i & 31;
            *reinterpret_cast<float4*>(&Wt[kk][c4 * 4]) =
                *reinterpret_cast<const float4*>(
                    W1 + (size_t)(koff + kc + kk) * D + c4 * 4);
        }
        __syncthreads();

#pragma unroll
        for (int kk = 0; kk < KC; kk++) {
            float af[8], bf[8];
            *reinterpret_cast<float4*>(af)     = *reinterpret_cast<float4*>(&Zt[kk][ty * 8]);
            *reinterpret_cast<float4*>(af + 4) = *reinterpret_cast<float4*>(&Zt[kk][ty * 8 + 4]);
            *reinterpret_cast<float4*>(bf)     = *reinterpret_cast<float4*>(&Wt[kk][tx * 8]);
            *reinterpret_cast<float4*>(bf + 4) = *reinterpret_cast<float4*>(&Wt[kk][tx * 8 + 4]);
#pragma unroll
            for (int i = 0; i < 8; i++)
#pragma unroll
                for (int j = 0; j < 8; j++)
                    acc[i][j] = fmaf(af[i], bf[j], acc[i][j]);
        }
    }

    // Epilogue: rows r0+ty*8+i, cols tx*8..tx*8+7, rounded to fp16.
    float bias[8];
#pragma unroll
    for (int j = 0; j < 8; j++) bias[j] = addb ? b1[tx * 8 + j] : 0.f;

#pragma unroll
    for (int i = 0; i < 8; i++) {
        int r = r0 + ty * 8 + i;
        if (r < N) {
            __half2 h[4];
#pragma unroll
            for (int j = 0; j < 4; j++)
                h[j] = __floats2half2_rn(acc[i][2 * j]     + bias[2 * j],
                                         acc[i][2 * j + 1] + bias[2 * j + 1]);
            // 8 halves = 16B aligned store (row stride 256B, offset tx*16B)
            *reinterpret_cast<uint4*>(out + (size_t)r * D + tx * 8) =
                *reinterpret_cast<uint4*>(h);
        }
    }
}

// 4 edges per warp. Lane l owns features [4l, 4l+4): loads 4 halves (8B)
// from each gathered row (fully coalesced 256B per row), half2 add+relu,
// fp32 dot with W2, then paired shfl reduction (10 SHFL per 4 edges).
__global__ __launch_bounds__(256) void edge_kernel(
    const int* __restrict__ row, const int* __restrict__ col,
    const float* __restrict__ W2, const float* __restrict__ b2,
    float* __restrict__ out, int E)
{
    const int lane = threadIdx.x & 31;
    const int warp = blockIdx.x * 8 + (threadIdx.x >> 5);
    const int e0 = warp * 4;
    if (e0 >= E) return;

    const float4 w2 = reinterpret_cast<const float4*>(W2)[lane];
    const float bias = b2[0];

    // Edge indices: 2 uniform LDG.128 per warp (tail-safe scalar path).
    int4 r4, c4;
    if (e0 + 3 < E) {
        r4 = *reinterpret_cast<const int4*>(row + e0);
        c4 = *reinterpret_cast<const int4*>(col + e0);
    } else {
        int last = E - 1;
        r4.x = row[e0];
        r4.y = row[min(e0 + 1, last)];
        r4.z = row[min(e0 + 2, last)];
        r4.w = row[min(e0 + 3, last)];
        c4.x = col[e0];
        c4.y = col[min(e0 + 1, last)];
        c4.z = col[min(e0 + 2, last)];
        c4.w = col[min(e0 + 3, last)];
    }

    // Front-batched gathers: 8 independent 8B/lane loads in flight.
    const uint2* __restrict__ Ah = reinterpret_cast<const uint2*>(g_Ah);
    const uint2* __restrict__ Bh = reinterpret_cast<const uint2*>(g_Bh);
    // row r -> uint2 index r*32 + lane (D=128 halves = 32 uint2 per row)
    const uint2 a0 = Ah[(size_t)r4.x * 32 + lane];
    const uint2 b0 = Bh[(size_t)c4.x * 32 + lane];
    const uint2 a1 = Ah[(size_t)r4.y * 32 + lane];
    const uint2 b1v = Bh[(size_t)c4.y * 32 + lane];
    const uint2 a2 = Ah[(size_t)r4.z * 32 + lane];
    const uint2 b2v = Bh[(size_t)c4.z * 32 + lane];
    const uint2 a3 = Ah[(size_t)r4.w * 32 + lane];
    const uint2 b3v = Bh[(size_t)c4.w * 32 + lane];

    const __half2 zero = __float2half2_rn(0.f);

    auto edge_dot = [&](uint2 a, uint2 b) -> float {
        __half2 al = *reinterpret_cast<__half2*>(&a.x);
        __half2 ah = *reinterpret_cast<__half2*>(&a.y);
        __half2 bl = *reinterpret_cast<__half2*>(&b.x);
        __half2 bh = *reinterpret_cast<__half2*>(&b.y);
        __half2 h0 = __hmax2(__hadd2(al, bl), zero);
        __half2 h1 = __hmax2(__hadd2(ah, bh), zero);
        float2 f0 = __half22float2(h0);
        float2 f1 = __half22float2(h1);
        return f0.x * w2.x + f0.y * w2.y + f1.x * w2.z + f1.y * w2.w;
    };

    float s0 = edge_dot(a0, b0);
    float s1 = edge_dot(a1, b1v);
    float s2 = edge_dot(a2, b2v);
    float s3 = edge_dot(a3, b3v);

    // Paired reduction: fold (s0,s1) and (s2,s3) into half-warp-resident
    // values, then 4-stage butterfly within 16-lane groups.
    const unsigned full = 0xffffffffu;
    const bool hi = (lane & 16) != 0;

    float va = hi ? s1 : s0;
    float oa = hi ? s0 : s1;
    va += __shfl_xor_sync(full, oa, 16);
    float vb = hi ? s3 : s2;
    float ob = hi ? s2 : s3;
    vb += __shfl_xor_sync(full, ob, 16);

#pragma unroll
    for (int off = 8; off > 0; off >>= 1) {
        va += __shfl_xor_sync(full, va, off);
        vb += __shfl_xor_sync(full, vb, off);
    }

    // lane 0: (e0, e0+2); lane 16: (e0+1, e0+3)
    if (lane == 0) {
        out[e0] = va + bias;
        if (e0 + 2 < E) out[e0 + 2] = vb + bias;
    } else if (lane == 16) {
        if (e0 + 1 < E) out[e0 + 1] = va + bias;
        if (e0 + 3 < E) out[e0 + 3] = vb + bias;
    }
}

extern "C" void kernel_launch(void* const* d_in, const int* in_sizes, int n_in,
                              void* d_out, int out_size)
{
    const float* z_drug = (const float*)d_in[0];
    const float* z_dis  = (const float*)d_in[1];
    const int*   row    = (const int*)  d_in[2];
    const int*   col    = (const int*)  d_in[3];
    const float* W1     = (const float*)d_in[4];
    const float* b1     = (const float*)d_in[5];
    const float* W2     = (const float*)d_in[6];
    const float* b2     = (const float*)d_in[7];
    float* out = (float*)d_out;

    const int n_drug = in_sizes[0] / D;
    const int n_dis  = in_sizes[1] / D;
    const int E      = in_sizes[2];

    __half *dA = nullptr, *dB = nullptr;
    cudaGetSymbolAddress((void**)&dA, g_Ah);
    cudaGetSymbolAddress((void**)&dB, g_Bh);

    // Phase 1: both node projections in ONE launch (fp32 math, fp16 store).
    const int tiles = (n_drug + 127) / 128 + (n_dis + 127) / 128;
    proj2_kernel<<<tiles, 256>>>(z_drug, z_dis, n_drug, n_dis, W1, b1, dA, dB);

    // Phase 2: per-edge gather + relu + dot(W2). 4 edges per warp.
    const int warps  = (E + 3) / 4;
    const int blocks = (warps + 7) / 8;
    edge_kernel<<<blocks, 256>>>(row, col, W2, b2, out, E);
}

// round 4
// speedup vs baseline: 3.9900x; 1.0004x over previous
#include <cuda_runtime.h>
#include <cuda_fp16.h>

#define D 128
#define MAX_DRUG 10000
#define MAX_DIS  15000
#define KC 16          // k-chunk per smem stage

// Projected embeddings stored in fp16 (computed in fp32, rounded once).
__device__ __half g_Ah[MAX_DRUG * D];   // z_drug    @ W1[0:128]  + b1
__device__ __half g_Bh[MAX_DIS  * D];   // z_disease @ W1[128:256]

// Fused projection: A = z_drug@W1_top + b1 and B = z_dis@W1_bot in one
// launch. One block per 128x128 output tile, 256 threads, 8x8 register
// tile per thread. Epilogue rounds to fp16.
__global__ __launch_bounds__(256) void proj2_kernel(
    const float* __restrict__ Zd, const float* __restrict__ Zs_,
    int n_drug, int n_dis,
    const float* __restrict__ W1, const float* __restrict__ b1,
    __half* __restrict__ A, __half* __restrict__ B)
{
    const int tiles_drug = (n_drug + 127) / 128;

    const float* Z;
    __half* out;
    int N, koff, addb;
    int tile = blockIdx.x;
    if (tile < tiles_drug) { Z = Zd;  out = A; N = n_drug; koff = 0;   addb = 1; }
    else { tile -= tiles_drug; Z = Zs_; out = B; N = n_dis; koff = 128; addb = 0; }
    const int r0 = tile * 128;

    __shared__ float Zt[KC][128];   // k-major (transposed Z tile)
    __shared__ float Wt[KC][128];

    const int t  = threadIdx.x;
    const int tx = t & 15;          // col group: cols tx*8 .. tx*8+7
    const int ty = t >> 4;          // row group: rows ty*8 .. ty*8+7

    float acc[8][8];
#pragma unroll
    for (int i = 0; i < 8; i++)
#pragma unroll
        for (int j = 0; j < 8; j++) acc[i][j] = 0.f;

    for (int kc = 0; kc < D; kc += KC) {
        __syncthreads();   // previous stage fully consumed

        // Z tile: rows r0..r0+127, k in [kc, kc+16). Transposed STS.
#pragma unroll
        for (int i = t; i < 512; i += 256) {
            int rr = i & 127;
            int k4 = i >> 7;
            float4 v = make_float4(0.f, 0.f, 0.f, 0.f);
            if (r0 + rr < N)
                v = *reinterpret_cast<const float4*>(
                        Z + (size_t)(r0 + rr) * D + kc + k4 * 4);
            Zt[k4 * 4 + 0][rr] = v.x;
            Zt[k4 * 4 + 1][rr] = v.y;
            Zt[k4 * 4 + 2][rr] = v.z;
            Zt[k4 * 4 + 3][rr] = v.w;
        }
        // W1 chunk: k rows [koff+kc, +16), all 128 cols. Coalesced float4.
#pragma unroll
        for (int i = t; i < 512; i += 256) {
            int kk = i >> 5;
            int c4 = i & 31;
            *reinterpret_cast<float4*>(&Wt[kk][c4 * 4]) =
                *reinterpret_cast<const float4*>(
                    W1 + (size_t)(koff + kc + kk) * D + c4 * 4);
        }
        __syncthreads();

#pragma unroll
        for (int kk = 0; kk < KC; kk++) {
            float af[8], bf[8];
            *reinterpret_cast<float4*>(af)     = *reinterpret_cast<float4*>(&Zt[kk][ty * 8]);
            *reinterpret_cast<float4*>(af + 4) = *reinterpret_cast<float4*>(&Zt[kk][ty * 8 + 4]);
            *reinterpret_cast<float4*>(bf)     = *reinterpret_cast<float4*>(&Wt[kk][tx * 8]);
            *reinterpret_cast<float4*>(bf + 4) = *reinterpret_cast<float4*>(&Wt[kk][tx * 8 + 4]);
#pragma unroll
            for (int i = 0; i < 8; i++)
#pragma unroll
                for (int j = 0; j < 8; j++)
                    acc[i][j] = fmaf(af[i], bf[j], acc[i][j]);
        }
    }

    // Epilogue: rows r0+ty*8+i, cols tx*8..tx*8+7, rounded to fp16.
    float bias[8];
#pragma unroll
    for (int j = 0; j < 8; j++) bias[j] = addb ? b1[tx * 8 + j] : 0.f;

#pragma unroll
    for (int i = 0; i < 8; i++) {
        int r = r0 + ty * 8 + i;
        if (r < N) {
            __half2 h[4];
#pragma unroll
            for (int j = 0; j < 4; j++)
                h[j] = __floats2half2_rn(acc[i][2 * j]     + bias[2 * j],
                                         acc[i][2 * j + 1] + bias[2 * j + 1]);
            *reinterpret_cast<uint4*>(out + (size_t)r * D + tx * 8) =
                *reinterpret_cast<uint4*>(h);
        }
    }
}

// 8 edges per warp, processed as 4 pairs. For pair p, lanes 0-15 handle
// edge e0+2p and lanes 16-31 handle e0+2p+1: one warp-wide LDG.128
// (16B/lane) fetches TWO full 256B rows. Dot in fp16 (dual HFMA2
// accumulators, depth 2), reduction in fp32 within 16-lane halves.
__global__ __launch_bounds__(256) void edge_kernel(
    const int* __restrict__ row, const int* __restrict__ col,
    const float* __restrict__ W2, const float* __restrict__ b2,
    float* __restrict__ out, int E)
{
    const int lane = threadIdx.x & 31;
    const int warp = blockIdx.x * 8 + (threadIdx.x >> 5);
    const int e0 = warp * 8;
    if (e0 >= E) return;

    const int  j  = lane & 15;        // 16B chunk within a row
    const bool hi = lane >= 16;       // which edge of the pair

    // W2 features [j*8, j*8+8) as 4 half2 (one-time conversion).
    const float4 wa = reinterpret_cast<const float4*>(W2)[j * 2];
    const float4 wb = reinterpret_cast<const float4*>(W2)[j * 2 + 1];
    const __half2 w0 = __floats2half2_rn(wa.x, wa.y);
    const __half2 w1 = __floats2half2_rn(wa.z, wa.w);
    const __half2 w2h = __floats2half2_rn(wb.x, wb.y);
    const __half2 w3 = __floats2half2_rn(wb.z, wb.w);
    const float bias = b2[0];

    // Edge indices: 4 uniform LDG.128 per warp (tail-safe scalar path).
    int4 r01, r45, c01, c45;
    if (e0 + 7 < E) {
        r01 = *reinterpret_cast<const int4*>(row + e0);
        r45 = *reinterpret_cast<const int4*>(row + e0 + 4);
        c01 = *reinterpret_cast<const int4*>(col + e0);
        c45 = *reinterpret_cast<const int4*>(col + e0 + 4);
    } else {
        const int last = E - 1;
        r01.x = row[e0];
        r01.y = row[min(e0 + 1, last)];
        r01.z = row[min(e0 + 2, last)];
        r01.w = row[min(e0 + 3, last)];
        r45.x = row[min(e0 + 4, last)];
        r45.y = row[min(e0 + 5, last)];
        r45.z = row[min(e0 + 6, last)];
        r45.w = row[min(e0 + 7, last)];
        c01.x = col[e0];
        c01.y = col[min(e0 + 1, last)];
        c01.z = col[min(e0 + 2, last)];
        c01.w = col[min(e0 + 3, last)];
        c45.x = col[min(e0 + 4, last)];
        c45.y = col[min(e0 + 5, last)];
        c45.z = col[min(e0 + 6, last)];
        c45.w = col[min(e0 + 7, last)];
    }

    // Per-half-warp row selection (32-bit index math; row = 16 uint4).
    const int ra0 = hi ? r01.y : r01.x;
    const int ra1 = hi ? r01.w : r01.z;
    const int ra2 = hi ? r45.y : r45.x;
    const int ra3 = hi ? r45.w : r45.z;
    const int ca0 = hi ? c01.y : c01.x;
    const int ca1 = hi ? c01.w : c01.z;
    const int ca2 = hi ? c45.y : c45.x;
    const int ca3 = hi ? c45.w : c45.z;

    const uint4* __restrict__ A16 = reinterpret_cast<const uint4*>(g_Ah);
    const uint4* __restrict__ B16 = reinterpret_cast<const uint4*>(g_Bh);

    // Front-batched: 8 independent LDG.128 in flight (each = 2 rows).
    const uint4 A0 = A16[ra0 * 16 + j];
    const uint4 B0 = B16[ca0 * 16 + j];
    const uint4 A1 = A16[ra1 * 16 + j];
    const uint4 B1 = B16[ca1 * 16 + j];
    const uint4 A2 = A16[ra2 * 16 + j];
    const uint4 B2 = B16[ca2 * 16 + j];
    const uint4 A3 = A16[ra3 * 16 + j];
    const uint4 B3 = B16[ca3 * 16 + j];

    const __half2 zero = __float2half2_rn(0.f);

    // relu(a+b) dot w2-chunk, fp16 HFMA2 with dual accumulators (depth 2),
    // fp32 cross-accumulator combine.
    auto pair_dot = [&](const uint4& a, const uint4& b) -> float {
        __half2 h0 = __hmax2(__hadd2(*reinterpret_cast<const __half2*>(&a.x),
                                     *reinterpret_cast<const __half2*>(&b.x)), zero);
        __half2 h1 = __hmax2(__hadd2(*reinterpret_cast<const __half2*>(&a.y),
                                     *reinterpret_cast<const __half2*>(&b.y)), zero);
        __half2 h2 = __hmax2(__hadd2(*reinterpret_cast<const __half2*>(&a.z),
                                     *reinterpret_cast<const __half2*>(&b.z)), zero);
        __half2 h3 = __hmax2(__hadd2(*reinterpret_cast<const __half2*>(&a.w),
                                     *reinterpret_cast<const __half2*>(&b.w)), zero);
        __half2 acc0 = __hfma2(h1, w1, __hmul2(h0, w0));
        __half2 acc1 = __hfma2(h3, w3, __hmul2(h2, w2h));
        float2 f0 = __half22float2(acc0);
        float2 f1 = __half22float2(acc1);
        return (f0.x + f0.y) + (f1.x + f1.y);
    };

    float s0 = pair_dot(A0, B0);
    float s1 = pair_dot(A1, B1);
    float s2 = pair_dot(A2, B2);
    float s3 = pair_dot(A3, B3);

    // Butterfly within 16-lane halves (both edges of each pair reduce
    // concurrently; xor offsets < 16 never cross the half-warp).
    const unsigned full = 0xffffffffu;
#pragma unroll
    for (int off = 8; off > 0; off >>= 1) {
        s0 += __shfl_xor_sync(full, s0, off);
        s1 += __shfl_xor_sync(full, s1, off);
        s2 += __shfl_xor_sync(full, s2, off);
        s3 += __shfl_xor_sync(full, s3, off);
    }

    // lane 0 holds even edges, lane 16 holds odd edges.
    if (lane == 0) {
        out[e0] = s0 + bias;
        if (e0 + 2 < E) out[e0 + 2] = s1 + bias;
        if (e0 + 4 < E) out[e0 + 4] = s2 + bias;
        if (e0 + 6 < E) out[e0 + 6] = s3 + bias;
    } else if (lane == 16) {
        if (e0 + 1 < E) out[e0 + 1] = s0 + bias;
        if (e0 + 3 < E) out[e0 + 3] = s1 + bias;
        if (e0 + 5 < E) out[e0 + 5] = s2 + bias;
        if (e0 + 7 < E) out[e0 + 7] = s3 + bias;
    }
}

extern "C" void kernel_launch(void* const* d_in, const int* in_sizes, int n_in,
                              void* d_out, int out_size)
{
    const float* z_drug = (const float*)d_in[0];
    const float* z_dis  = (const float*)d_in[1];
    const int*   row    = (const int*)  d_in[2];
    const int*   col    = (const int*)  d_in[3];
    const float* W1     = (const float*)d_in[4];
    const float* b1     = (const float*)d_in[5];
    const float* W2     = (const float*)d_in[6];
    const float* b2     = (const float*)d_in[7];
    float* out = (float*)d_out;

    const int n_drug = in_sizes[0] / D;
    const int n_dis  = in_sizes[1] / D;
    const int E      = in_sizes[2];

    __half *dA = nullptr, *dB = nullptr;
    cudaGetSymbolAddress((void**)&dA, g_Ah);
    cudaGetSymbolAddress((void**)&dB, g_Bh);

    // Phase 1: both node projections in ONE launch (fp32 math, fp16 store).
    const int tiles = (n_drug + 127) / 128 + (n_dis + 127) / 128;
    proj2_kernel<<<tiles, 256>>>(z_drug, z_dis, n_drug, n_dis, W1, b1, dA, dB);

    // Phase 2: per-edge gather + relu + dot(W2). 8 edges per warp.
    const int warps  = (E + 7) / 8;
    const int blocks = (warps + 7) / 8;
    edge_kernel<<<blocks, 256>>>(row, col, W2, b2, out, E);
}